// round 17
// baseline (speedup 1.0000x reference)
#include <cuda_runtime.h>
#include <cuda_fp16.h>
#include <cstdint>
#include <cstddef>

// Shapes fixed by the problem: B=32, S=2048, E=D=1024.
#define BATCH 32
#define SEQ   2048
#define EDIM  1024
#define NROWS (BATCH * SEQ)   // 65536
#define NTILES (NROWS / 128)  // 512
#define PERSIST_CTAS 296      // 148 SMs * 2 CTAs/SM

// ---------------- scratch (static __device__ — no allocation allowed) ----------------
__device__ __half g_Ah[(size_t)NROWS * EDIM];    // 128 MB  enc fp16
__device__ __half g_Bh[(size_t)EDIM * EDIM];     // w1^T fp16  [n=e][k=d]
__device__ float g_q[BATCH * EDIM];              // q = dec@w2 + b2 + b1
__device__ float g_scores[NROWS];
__device__ unsigned g_tile;                      // persistent-CTA work ticket

// ---------------- kernel 1: prep = conv enc + conv w1 + query proj + ticket reset ----
// blocks [0,8192): enc fp32->fp16 ; [8192,12288): w1 transpose->fp16 ;
// [12288,12416): query projection (qb = blk-12288: b = qb>>2, e-chunk = qb&3).
__global__ void prep_kernel(const float* __restrict__ enc,
                            const float* __restrict__ w1,
                            const float* __restrict__ dec,
                            const float* __restrict__ w2,
                            const float* __restrict__ b2,
                            const float* __restrict__ b1) {
    const int blk = blockIdx.x;
    const int t = threadIdx.x;
    if (blk == 0 && t == 0) g_tile = 0;

    if (blk < 8192) {
        const int n4 = NROWS * EDIM / 4;
        for (int idx = blk * 256 + t; idx < n4; idx += 8192 * 256) {
            float4 v = reinterpret_cast<const float4*>(enc)[idx];
            __half2* Hp = reinterpret_cast<__half2*>(g_Ah) + idx * 2;
            Hp[0] = __halves2half2(__float2half(v.x), __float2half(v.y));
            Hp[1] = __halves2half2(__float2half(v.z), __float2half(v.w));
        }
    } else if (blk < 12288) {
        int idx = (blk - 8192) * 256 + t;       // over 1<<20
        int nn = idx >> 10;                     // output col e -> B row
        int kk = idx & 1023;                    // input dim d  -> B col
        g_Bh[idx] = __float2half(w1[(kk << 10) + nn]);
    } else {
        const int qb = blk - 12288;
        const int b = qb >> 2;
        const int e = (qb & 3) * 256 + t;
        __shared__ float sd[EDIM];
        for (int i = t; i < EDIM; i += 256) sd[i] = dec[b * EDIM + i];
        __syncthreads();
        float acc = b2[e] + b1[e];
#pragma unroll 8
        for (int d = 0; d < EDIM; ++d) acc += sd[d] * w2[(d << 10) + e];
        g_q[b * EDIM + e] = acc;
    }
}

// ---------------- kernel 2: persistent pipelined fp16 GEMM + fused tanh·v -> scores ----
#define LDSM4(R0, R1, R2, R3, addr)                                              \
    asm volatile("ldmatrix.sync.aligned.m8n8.x4.shared.b16 {%0,%1,%2,%3}, [%4];" \
                 : "=r"(R0), "=r"(R1), "=r"(R2), "=r"(R3) : "r"(addr))

#define MMA16816(d, a, b0r, b1r)                                                  \
    asm volatile("mma.sync.aligned.m16n8k16.row.col.f32.f16.f16.f32 "             \
                 "{%0,%1,%2,%3}, {%4,%5,%6,%7}, {%8,%9}, {%0,%1,%2,%3};"          \
                 : "+f"((d)[0]), "+f"((d)[1]), "+f"((d)[2]), "+f"((d)[3])         \
                 : "r"((a)[0]), "r"((a)[1]), "r"((a)[2]), "r"((a)[3]),            \
                   "r"(b0r), "r"(b1r))

#define CP_ASYNC16(dst, src)                                                     \
    asm volatile("cp.async.cg.shared.global [%0], [%1], 16;" :: "r"(dst), "l"(src))
#define CP_COMMIT() asm volatile("cp.async.commit_group;" ::: "memory")
#define CP_WAIT1()  asm volatile("cp.async.wait_group 1;" ::: "memory")

// Chunk = (np, k0): tiles {A 128x64h, B 128x64h}, 128-B rows, SW128 swizzle
// (phys = off ^ ((row & 7) << 4)).  3-stage ring.  128 chunks = 8 np * 16 k-chunks.
#define TILE_BYTES 16384
#define STG_BYTES  32768
#define OFF_Q   98304
#define OFF_V   102400
#define OFF_ACC 106496
#define OFF_T   107008
#define SMEM_TOTAL 107024

__global__ void __launch_bounds__(256, 2) scores_kernel(const float* __restrict__ v) {
    extern __shared__ char smem[];
    uint32_t sb;
    asm("{ .reg .u64 t; cvta.to.shared.u64 t, %1; cvt.u32.u64 %0, t; }"
        : "=r"(sb) : "l"(smem));

    const int tid  = threadIdx.x;
    const int lane = tid & 31;
    const int wid  = tid >> 5;
    const int wm   = wid >> 1;   // 0..3
    const int wn   = wid & 1;    // 0..1

    float* s_q   = reinterpret_cast<float*>(smem + OFF_Q);
    float* s_v   = reinterpret_cast<float*>(smem + OFF_V);
    float* s_acc = reinterpret_cast<float*>(smem + OFF_ACC);
    unsigned* s_t = reinterpret_cast<unsigned*>(smem + OFF_T);

    for (int i = tid; i < EDIM; i += 256) s_v[i] = v[i];

    // ---- ldmatrix addresses (SW128 swizzled, per-thread constants) ----
    const int row_a = wm * 32 + (lane & 15);
    const int ga    = lane >> 4;
    const int xa    = row_a & 7;
    uint32_t a_off[4];
#pragma unroll
    for (int kk = 0; kk < 4; ++kk)
        a_off[kk] = (uint32_t)(row_a * 128 + (((2 * kk + ga) ^ xa) << 4));
    const int row_b = wn * 64 + ((lane >> 4) << 3) + (lane & 7);
    const int gb    = (lane >> 3) & 1;
    const int xb    = row_b & 7;
    uint32_t b_off[4];
#pragma unroll
    for (int kk = 0; kk < 4; ++kk)
        b_off[kk] = (uint32_t)(row_b * 128 + (((2 * kk + gb) ^ xb) << 4));

    // ---- staging: 1024 uint4 slots per tile, 4 per thread ----
    auto stage = [&](int row0, int it) {
        const int np = it >> 4;
        const int k0 = (it & 15) << 6;        // halves
        const uint32_t base = sb + (uint32_t)(it % 3) * STG_BYTES;
#pragma unroll
        for (int j = 0; j < 4; ++j) {
            const int i = tid + (j << 8);
            const int r = i >> 3, g = i & 7;
            const uint32_t doff = (uint32_t)(r * 128 + ((g ^ (r & 7)) << 4));
            CP_ASYNC16(base + doff,
                       g_Ah + (((size_t)(row0 + r)) << 10) + k0 + g * 8);
            CP_ASYNC16(base + TILE_BYTES + doff,
                       g_Bh + (((size_t)((np << 7) + r)) << 10) + k0 + g * 8);
        }
    };

    float acc[16][4];

    for (;;) {
        if (tid == 0) s_t[0] = atomicAdd(&g_tile, 1u);
        __syncthreads();                 // broadcast ticket; fences previous tile
        const int tile = (int)s_t[0];
        if (tile >= NTILES) break;
        const int row0 = tile << 7;
        const int b    = row0 >> 11;

        for (int i = tid; i < EDIM; i += 256) s_q[i] = g_q[(b << 10) + i];
        if (tid < 128) s_acc[tid] = 0.0f;

        stage(row0, 0); CP_COMMIT();
        stage(row0, 1); CP_COMMIT();

#pragma unroll 1
        for (int c = 0; c < 128; ++c) {
            if ((c & 15) == 0) {
#pragma unroll
                for (int i = 0; i < 16; ++i) {
                    acc[i][0] = 0.f; acc[i][1] = 0.f; acc[i][2] = 0.f; acc[i][3] = 0.f;
                }
            }

            CP_WAIT1();          // chunk c resident
            __syncthreads();     // all warps done reading buffer (c-1)%3

            if (c + 2 < 128) stage(row0, c + 2);   // overlaps MMA body
            CP_COMMIT();

            const uint32_t a_base = sb + (uint32_t)(c % 3) * STG_BYTES;
            const uint32_t b_base = a_base + TILE_BYTES;
#pragma unroll
            for (int kk = 0; kk < 4; ++kk) {
                // hoist all fragment loads (independent) ahead of the MMA block
                uint32_t a0[4], a1[4], b0[4], b1[4], b2[4], b3[4];
                LDSM4(a0[0], a0[1], a0[2], a0[3], a_base + a_off[kk]);
                LDSM4(a1[0], a1[1], a1[2], a1[3], a_base + a_off[kk] + 2048);
                LDSM4(b0[0], b0[1], b0[2], b0[3], b_base + b_off[kk]);
                LDSM4(b1[0], b1[1], b1[2], b1[3], b_base + b_off[kk] + 2048);
                LDSM4(b2[0], b2[1], b2[2], b2[3], b_base + b_off[kk] + 4096);
                LDSM4(b3[0], b3[1], b3[2], b3[3], b_base + b_off[kk] + 6144);
                // identity mapping: acc[2p] = n-cols [16p,16p+8), acc[2p+1] = [16p+8,16p+16)
                MMA16816(acc[0],  a0, b0[0], b0[1]);
                MMA16816(acc[2],  a0, b1[0], b1[1]);
                MMA16816(acc[4],  a0, b2[0], b2[1]);
                MMA16816(acc[6],  a0, b3[0], b3[1]);
                MMA16816(acc[1],  a0, b0[2], b0[3]);
                MMA16816(acc[3],  a0, b1[2], b1[3]);
                MMA16816(acc[5],  a0, b2[2], b2[3]);
                MMA16816(acc[7],  a0, b3[2], b3[3]);
                MMA16816(acc[8],  a1, b0[0], b0[1]);
                MMA16816(acc[10], a1, b1[0], b1[1]);
                MMA16816(acc[12], a1, b2[0], b2[1]);
                MMA16816(acc[14], a1, b3[0], b3[1]);
                MMA16816(acc[9],  a1, b0[2], b0[3]);
                MMA16816(acc[11], a1, b1[2], b1[3]);
                MMA16816(acc[13], a1, b2[2], b2[3]);
                MMA16816(acc[15], a1, b3[2], b3[3]);
            }

            if ((c & 15) == 15) {
                // epilogue for n-chunk np: score_part[row] += sum_n tanh(C + q) * v
                // accumulator for col offset 8*nf is acc[mf*8 + nf]  (identity mapping)
                const int np = c >> 4;
                float part[4] = {0.f, 0.f, 0.f, 0.f};
                const int ncol0 = (np << 7) + wn * 64 + ((lane & 3) << 1);
#pragma unroll
                for (int mf = 0; mf < 2; ++mf) {
#pragma unroll
                    for (int nf = 0; nf < 8; ++nf) {
                        int n = ncol0 + (nf << 3);
                        float q0 = s_q[n], q1 = s_q[n + 1];
                        float v0 = s_v[n], v1 = s_v[n + 1];
                        const float* cc = acc[mf * 8 + nf];
                        part[mf * 2 + 0] += tanhf(cc[0] + q0) * v0 + tanhf(cc[1] + q1) * v1;
                        part[mf * 2 + 1] += tanhf(cc[2] + q0) * v0 + tanhf(cc[3] + q1) * v1;
                    }
                }
                const int rb = wm * 32 + (lane >> 2);
                atomicAdd(&s_acc[rb],      part[0]);
                atomicAdd(&s_acc[rb + 8],  part[1]);
                atomicAdd(&s_acc[rb + 16], part[2]);
                atomicAdd(&s_acc[rb + 24], part[3]);
            }
        }

        __syncthreads();
        if (tid < 128) g_scores[row0 + tid] = s_acc[tid];   // +bv dropped (softmax-inv.)
    }
}

// ---------------- kernel 3: fused softmax + context ----------------
// Each (chunk, b) block recomputes the row softmax stats (cheap) and accumulates
// context over unnormalized exp, scaling by 1/sum at the end.
__global__ void context_kernel(const float* __restrict__ enc, float* __restrict__ out) {
    const int b = blockIdx.y;
    const int chunk = blockIdx.x;      // 4 chunks of 256 e
    const int t = threadIdx.x;
    const int sub = t >> 6;            // 4 s-partitions
    const int tt = t & 63;

    __shared__ float sa[SEQ];
    __shared__ float red[256];
    __shared__ float4 part[3][64];

    const float* sc = g_scores + b * SEQ;
    for (int i = t; i < SEQ; i += 256) sa[i] = sc[i];
    __syncthreads();

    float m = -1e30f;
    for (int i = t; i < SEQ; i += 256) m = fmaxf(m, sa[i]);
    red[t] = m; __syncthreads();
#pragma unroll
    for (int o = 128; o > 0; o >>= 1) {
        if (t < o) red[t] = fmaxf(red[t], red[t + o]);
        __syncthreads();
    }
    const float mx = red[0];
    __syncthreads();

    float s = 0.f;
    for (int i = t; i < SEQ; i += 256) {
        float e = expf(sa[i] - mx);
        sa[i] = e;                      // unnormalized weight
        s += e;
    }
    red[t] = s; __syncthreads();
#pragma unroll
    for (int o = 128; o > 0; o >>= 1) {
        if (t < o) red[t] += red[t + o];
        __syncthreads();
    }
    const float inv = 1.0f / red[0];
    __syncthreads();

    const float4* ep = reinterpret_cast<const float4*>(enc) +
                       (size_t)b * SEQ * 256 + chunk * 64 + tt;
    float4 acc = {0.f, 0.f, 0.f, 0.f};
    const int s0 = sub * 512;
#pragma unroll 8
    for (int ss = s0; ss < s0 + 512; ++ss) {
        float a = sa[ss];
        float4 x = ep[(size_t)ss * 256];
        acc.x += a * x.x; acc.y += a * x.y; acc.z += a * x.z; acc.w += a * x.w;
    }
    if (sub) part[sub - 1][tt] = acc;
    __syncthreads();
    if (sub == 0) {
#pragma unroll
        for (int j = 0; j < 3; ++j) {
            float4 p = part[j][tt];
            acc.x += p.x; acc.y += p.y; acc.z += p.z; acc.w += p.w;
        }
        acc.x *= inv; acc.y *= inv; acc.z *= inv; acc.w *= inv;
        reinterpret_cast<float4*>(out)[b * 256 + chunk * 64 + tt] = acc;
    }
}

// ---------------- launch ----------------
extern "C" void kernel_launch(void* const* d_in, const int* in_sizes, int n_in,
                              void* d_out, int out_size) {
    const float* enc = (const float*)d_in[0];   // [32,2048,1024]
    const float* dec = (const float*)d_in[1];   // [32,1,1024]
    const float* w1  = (const float*)d_in[2];   // [1024,1024]
    const float* b1  = (const float*)d_in[3];   // [1024]
    const float* w2  = (const float*)d_in[4];   // [1024,1024]
    const float* b2  = (const float*)d_in[5];   // [1024]
    const float* v   = (const float*)d_in[6];   // [1024,1]
    // d_in[7] = bv: softmax-invariant, unused.
    float* out = (float*)d_out;                 // [32,1024]

    cudaFuncSetAttribute(scores_kernel,
                         cudaFuncAttributeMaxDynamicSharedMemorySize, SMEM_TOTAL);

    prep_kernel<<<12416, 256>>>(enc, w1, dec, w2, b2, b1);
    scores_kernel<<<PERSIST_CTAS, 256, SMEM_TOTAL>>>(v);
    context_kernel<<<dim3(4, BATCH), 256>>>(enc, out);
}